// round 5
// baseline (speedup 1.0000x reference)
#include <cuda_runtime.h>
#include <cstdint>

// Z gate (DIM=2) on qudits (0,5,10) of L=14: diagonal phase = parity sign flip.
// sign[n] = (-1)^(bit13(n) ^ bit8(n) ^ bit3(n)); out = [2,N,B] {±xr, ±xi}.
// Persistent grid-stride stream kernel: no wave transitions, front-batched
// LDG.128 (MLP=8 per iter), .cs reads (no reuse), default stores (L2 buffers
// write bursts).

static constexpr int N_ROWS = 16384;
static constexpr int B_COLS = 2048;
static constexpr long long TOTAL = (long long)N_ROWS * B_COLS;   // 33,554,432 floats
static constexpr int TOTAL4 = (int)(TOTAL / 4);                  // 8,388,608 uint4
static constexpr int ITEMS = 4;                                  // uint4-pairs per iter
static constexpr int THREADS = 256;
static constexpr int TILE = THREADS * ITEMS;                     // 1024 uint4 per iter
static constexpr int NUM_TILES = TOTAL4 / TILE;                  // 8192, exact
static constexpr int GRID = 148 * 8;                             // persistent: 1184 CTAs

__device__ __forceinline__ uint4 ldcs4(const uint4* p) {
    uint4 v;
    asm volatile("ld.global.cs.v4.u32 {%0,%1,%2,%3}, [%4];"
                 : "=r"(v.x), "=r"(v.y), "=r"(v.z), "=r"(v.w) : "l"(p));
    return v;
}

__global__ void __launch_bounds__(THREADS)
z_phase_kernel(const uint4* __restrict__ xr,
               const uint4* __restrict__ xi,
               uint4* __restrict__ out_r,
               uint4* __restrict__ out_i)
{
    for (int tile = blockIdx.x; tile < NUM_TILES; tile += GRID) {
        int base = tile * TILE + threadIdx.x;

        int idx[ITEMS];
        uint4 a[ITEMS], b[ITEMS];

        // Front-batched loads: 8 independent LDG.128 in flight before stores.
#pragma unroll
        for (int k = 0; k < ITEMS; k++) {
            idx[k] = base + k * THREADS;
            a[k] = ldcs4(xr + idx[k]);
        }
#pragma unroll
        for (int k = 0; k < ITEMS; k++)
            b[k] = ldcs4(xi + idx[k]);

#pragma unroll
        for (int k = 0; k < ITEMS; k++) {
            // element index = idx*4; row n = idx >> 9 (B=2048 floats/row)
            unsigned n = ((unsigned)idx[k]) >> 9;
            unsigned mask = (((n >> 13) ^ (n >> 8) ^ (n >> 3)) & 1u) << 31;
            a[k].x ^= mask; a[k].y ^= mask; a[k].z ^= mask; a[k].w ^= mask;
            b[k].x ^= mask; b[k].y ^= mask; b[k].z ^= mask; b[k].w ^= mask;
        }

#pragma unroll
        for (int k = 0; k < ITEMS; k++)
            out_r[idx[k]] = a[k];
#pragma unroll
        for (int k = 0; k < ITEMS; k++)
            out_i[idx[k]] = b[k];
    }
}

extern "C" void kernel_launch(void* const* d_in, const int* in_sizes, int n_in,
                              void* d_out, int out_size)
{
    const uint4* xr = (const uint4*)d_in[0];
    const uint4* xi = (const uint4*)d_in[1];
    float* out = (float*)d_out;
    uint4* out_r = (uint4*)out;                 // [N, B] real part
    uint4* out_i = (uint4*)(out + TOTAL);       // [N, B] imag part

    z_phase_kernel<<<GRID, THREADS>>>(xr, xi, out_r, out_i);
}

// round 6
// speedup vs baseline: 1.0776x; 1.0776x over previous
#include <cuda_runtime.h>
#include <cstdint>

// Z gate (DIM=2) on qudits (0,5,10) of L=14: diagonal phase = parity sign flip.
// sign[n] = (-1)^(bit13(n) ^ bit8(n) ^ bit3(n)); out = [2,N,B] {±xr, ±xi}.
//
// Pure 512 MiB stream at the mixed-RW HBM wall. Best measured config:
// one uint4-pair per thread, full grid (32768 blocks), high occupancy,
// .cs (evict-first) loads since input has zero reuse, default stores so L2
// buffers write bursts.

static constexpr int N_ROWS = 16384;
static constexpr int B_COLS = 2048;
static constexpr long long TOTAL = (long long)N_ROWS * B_COLS;   // 33,554,432 floats
static constexpr int TOTAL4 = (int)(TOTAL / 4);                  // 8,388,608 uint4

__device__ __forceinline__ uint4 ldcs4(const uint4* p) {
    uint4 v;
    asm volatile("ld.global.cs.v4.u32 {%0,%1,%2,%3}, [%4];"
                 : "=r"(v.x), "=r"(v.y), "=r"(v.z), "=r"(v.w) : "l"(p));
    return v;
}

__global__ void __launch_bounds__(256)
z_phase_kernel(const uint4* __restrict__ xr,
               const uint4* __restrict__ xi,
               uint4* __restrict__ out_r,
               uint4* __restrict__ out_i)
{
    int idx = blockIdx.x * blockDim.x + threadIdx.x;   // float4 index
    if (idx >= TOTAL4) return;

    // element index = idx*4; row n = (idx*4) >> 11 = idx >> 9 (B=2048 floats/row)
    unsigned n = ((unsigned)idx) >> 9;
    unsigned mask = (((n >> 13) ^ (n >> 8) ^ (n >> 3)) & 1u) << 31;

    uint4 a = ldcs4(xr + idx);
    uint4 b = ldcs4(xi + idx);

    a.x ^= mask; a.y ^= mask; a.z ^= mask; a.w ^= mask;
    b.x ^= mask; b.y ^= mask; b.z ^= mask; b.w ^= mask;

    out_r[idx] = a;
    out_i[idx] = b;
}

extern "C" void kernel_launch(void* const* d_in, const int* in_sizes, int n_in,
                              void* d_out, int out_size)
{
    const uint4* xr = (const uint4*)d_in[0];
    const uint4* xi = (const uint4*)d_in[1];
    float* out = (float*)d_out;
    uint4* out_r = (uint4*)out;                 // [N, B] real part
    uint4* out_i = (uint4*)(out + TOTAL);       // [N, B] imag part

    const int threads = 256;
    const int blocks = TOTAL4 / threads;        // 32768, exact (no tail)
    z_phase_kernel<<<blocks, threads>>>(xr, xi, out_r, out_i);
}

// round 7
// speedup vs baseline: 1.0835x; 1.0055x over previous
#include <cuda_runtime.h>
#include <cstdint>

// Z gate (DIM=2) on qudits (0,5,10) of L=14: diagonal phase = parity sign flip.
// sign[n] = (-1)^(bit13(n) ^ bit8(n) ^ bit3(n)); out = [2,N,B] {±xr, ±xi}.
//
// Pure 512 MiB stream at the mixed-RW HBM wall (~6.4 TB/s measured across all
// prior variants). This round: 256-bit vector accesses (sm_100+ LDG.E.256 /
// STG.E.256 via ld/st.global.v8.b32) — 1KB per warp request — to present
// longer contiguous bursts to the DRAM controllers. .cs loads (zero reuse),
// default stores (L2 buffers write bursts).

static constexpr int N_ROWS = 16384;
static constexpr int B_COLS = 2048;
static constexpr long long TOTAL = (long long)N_ROWS * B_COLS;   // 33,554,432 floats
static constexpr int TOTAL8 = (int)(TOTAL / 8);                  // 4,194,304 32B-vecs

struct v8 { uint32_t r[8]; };

__device__ __forceinline__ v8 ldcs8(const uint32_t* p) {
    v8 v;
    asm volatile("ld.global.cs.v8.b32 {%0,%1,%2,%3,%4,%5,%6,%7}, [%8];"
                 : "=r"(v.r[0]), "=r"(v.r[1]), "=r"(v.r[2]), "=r"(v.r[3]),
                   "=r"(v.r[4]), "=r"(v.r[5]), "=r"(v.r[6]), "=r"(v.r[7])
                 : "l"(p));
    return v;
}
__device__ __forceinline__ void st8(uint32_t* p, const v8& v) {
    asm volatile("st.global.v8.b32 [%0], {%1,%2,%3,%4,%5,%6,%7,%8};"
                 :: "l"(p),
                    "r"(v.r[0]), "r"(v.r[1]), "r"(v.r[2]), "r"(v.r[3]),
                    "r"(v.r[4]), "r"(v.r[5]), "r"(v.r[6]), "r"(v.r[7])
                 : "memory");
}

__global__ void __launch_bounds__(256)
z_phase_kernel(const uint32_t* __restrict__ xr,
               const uint32_t* __restrict__ xi,
               uint32_t* __restrict__ out_r,
               uint32_t* __restrict__ out_i)
{
    int idx = blockIdx.x * blockDim.x + threadIdx.x;   // 8-float vector index
    if (idx >= TOTAL8) return;

    // element index = idx*8; row n = (idx*8) >> 11 = idx >> 8 (B=2048 floats/row)
    unsigned n = ((unsigned)idx) >> 8;
    unsigned mask = (((n >> 13) ^ (n >> 8) ^ (n >> 3)) & 1u) << 31;

    const uint32_t* pa = xr + (size_t)idx * 8;
    const uint32_t* pb = xi + (size_t)idx * 8;

    v8 a = ldcs8(pa);
    v8 b = ldcs8(pb);

#pragma unroll
    for (int k = 0; k < 8; k++) { a.r[k] ^= mask; b.r[k] ^= mask; }

    st8(out_r + (size_t)idx * 8, a);
    st8(out_i + (size_t)idx * 8, b);
}

extern "C" void kernel_launch(void* const* d_in, const int* in_sizes, int n_in,
                              void* d_out, int out_size)
{
    const uint32_t* xr = (const uint32_t*)d_in[0];
    const uint32_t* xi = (const uint32_t*)d_in[1];
    uint32_t* out = (uint32_t*)d_out;
    uint32_t* out_r = out;                       // [N, B] real part
    uint32_t* out_i = out + TOTAL;               // [N, B] imag part

    const int threads = 256;
    const int blocks = TOTAL8 / threads;         // 16384, exact (no tail)
    z_phase_kernel<<<blocks, threads>>>(xr, xi, out_r, out_i);
}